// round 1
// baseline (speedup 1.0000x reference)
#include <cuda_runtime.h>
#include <math.h>

// ---------------- model dims ----------------
#define S_LEN   1024
#define H_DIM   4096
#define N_HEADS 32
#define HEAD_DIM 128
#define FFN_DIM 11008
#define N_LAYERS 2
#define OUT_DIM 512

// ---------------- workspace ----------------
// floats: h, a, q, k, v, o  (S*H each) ; gate, up (S*F each) ; att (NH*S*S)
#define SZ_SH  (4194304L)          // S*H
#define SZ_SF  (11272192L)         // S*F
#define SZ_ATT (33554432L)         // NH*S*S

#define OFF_H   (0L)
#define OFF_A   (1L*SZ_SH)
#define OFF_Q   (2L*SZ_SH)
#define OFF_K   (3L*SZ_SH)
#define OFF_V   (4L*SZ_SH)
#define OFF_O   (5L*SZ_SH)
#define OFF_G   (6L*SZ_SH)
#define OFF_U   (6L*SZ_SH + SZ_SF)
#define OFF_ATT (6L*SZ_SH + 2L*SZ_SF)

__device__ float g_ws[6L*4194304L + 2L*11272192L + 33554432L];

// ---------------- elementwise kernels ----------------
__global__ void embed_kernel(const int* __restrict__ x, const float* __restrict__ emb,
                             float* __restrict__ h) {
    long idx = (long)blockIdx.x * blockDim.x + threadIdx.x;  // S*H
    int s = (int)(idx >> 12);
    int j = (int)(idx & 4095);
    h[idx] = emb[(long)x[s] * H_DIM + j];
}

__global__ void rmsnorm_kernel(const float* __restrict__ in, const float* __restrict__ w,
                               float* __restrict__ out) {
    int row = blockIdx.x;
    const float4* ip = (const float4*)(in + (long)row * H_DIM);
    const float4* wp = (const float4*)w;
    float4* op = (float4*)(out + (long)row * H_DIM);
    int t = threadIdx.x;
    float ss = 0.f;
    float4 va[4];
#pragma unroll
    for (int u = 0; u < 4; u++) {
        va[u] = ip[t + u * 256];
        ss += va[u].x*va[u].x + va[u].y*va[u].y + va[u].z*va[u].z + va[u].w*va[u].w;
    }
    __shared__ float red[256];
    red[t] = ss; __syncthreads();
    for (int s2 = 128; s2 > 0; s2 >>= 1) {
        if (t < s2) red[t] += red[t + s2];
        __syncthreads();
    }
    float scale = rsqrtf(red[0] / (float)H_DIM + 1e-6f);
#pragma unroll
    for (int u = 0; u < 4; u++) {
        int i = t + u * 256;
        float4 a = va[u], ww = wp[i];
        float4 r;
        r.x = a.x * scale * ww.x; r.y = a.y * scale * ww.y;
        r.z = a.z * scale * ww.z; r.w = a.w * scale * ww.w;
        op[i] = r;
    }
}

__global__ void rope_kernel(float* __restrict__ q) {
    long idx = (long)blockIdx.x * blockDim.x + threadIdx.x;  // S*NH*64
    int i = (int)(idx & 63);
    int h = (int)((idx >> 6) & 31);
    int s = (int)(idx >> 11);
    long base = (long)s * H_DIM + h * HEAD_DIM;
    double inv = pow(10000.0, -(double)i / 64.0);
    double ang = (double)s * inv;
    float c = (float)cos(ang), sn = (float)sin(ang);
    float x1 = q[base + i], x2 = q[base + i + 64];
    q[base + i]      = x1 * c - x2 * sn;
    q[base + i + 64] = x2 * c + x1 * sn;
}

__global__ void softmax_kernel(float* __restrict__ att) {
    long row = blockIdx.x;  // NH*S rows of length S
    float4* p4 = (float4*)(att + row * (long)S_LEN);
    int t = threadIdx.x;
    float4 a = p4[t];
    float m = fmaxf(fmaxf(a.x, a.y), fmaxf(a.z, a.w));
    __shared__ float red[256];
    red[t] = m; __syncthreads();
    for (int s2 = 128; s2 > 0; s2 >>= 1) {
        if (t < s2) red[t] = fmaxf(red[t], red[t + s2]);
        __syncthreads();
    }
    m = red[0];
    __syncthreads();
    a.x = expf(a.x - m); a.y = expf(a.y - m);
    a.z = expf(a.z - m); a.w = expf(a.w - m);
    red[t] = a.x + a.y + a.z + a.w; __syncthreads();
    for (int s2 = 128; s2 > 0; s2 >>= 1) {
        if (t < s2) red[t] += red[t + s2];
        __syncthreads();
    }
    float inv = 1.0f / red[0];
    a.x *= inv; a.y *= inv; a.z *= inv; a.w *= inv;
    p4[t] = a;
}

__global__ void silu_mul_kernel(const float* __restrict__ g, const float* __restrict__ u,
                                float* __restrict__ out) {
    long idx = (long)blockIdx.x * blockDim.x + threadIdx.x;  // S*F
    float x = g[idx];
    float s = x / (1.0f + expf(-x));
    out[idx] = s * u[idx];
}

// ---------------- SGEMM NN (C[M,N] = A[M,K] * B[K,N], row-major, strided batch) ----------------
// EPI: 0 = C=AB ; 1 = C=AB+D ; 2 = C=AB+bias[n]
#define STORE_AT(buf, v) do { As[buf][acol+0][arow]=(v).x; As[buf][acol+1][arow]=(v).y; \
                              As[buf][acol+2][arow]=(v).z; As[buf][acol+3][arow]=(v).w; } while(0)

template <int EPI>
__global__ __launch_bounds__(256)
void sgemm_nn(int M, int N, int K,
              const float* __restrict__ A, int lda, long batA,
              const float* __restrict__ B, int ldb, long batB,
              float* __restrict__ C, int ldc, long batC,
              const float* __restrict__ D, long batD,
              const float* __restrict__ bias) {
    int bz = blockIdx.z;
    A += (long)bz * batA; B += (long)bz * batB; C += (long)bz * batC;
    if (EPI == 1) D += (long)bz * batD;

    const int m0 = blockIdx.y * 128;
    const int n0 = blockIdx.x * 128;
    const int tid = threadIdx.x;

    __shared__ float As[2][8][128];
    __shared__ float Bs[2][8][128];

    const int arow = tid >> 1;
    const int acol = (tid & 1) * 4;
    const int brow = tid >> 5;
    const int bcol = (tid & 31) * 4;
    const int ty = tid >> 4;
    const int tx = tid & 15;

    float acc[8][8];
#pragma unroll
    for (int i = 0; i < 8; i++)
#pragma unroll
        for (int j = 0; j < 8; j++) acc[i][j] = 0.f;

    const float* Ap = A + (long)(m0 + arow) * lda + acol;
    const float* Bp = B + (long)brow * ldb + n0 + bcol;

    const int NT = K / 8;
    float4 av = *(const float4*)Ap;
    float4 bv = *(const float4*)Bp;
    STORE_AT(0, av);
    *(float4*)&Bs[0][brow][bcol] = bv;
    __syncthreads();

    for (int kt = 0; kt < NT; kt++) {
        int cur = kt & 1;
        float4 a2, b2;
        if (kt + 1 < NT) {
            a2 = *(const float4*)(Ap + (kt + 1) * 8);
            b2 = *(const float4*)(Bp + (long)(kt + 1) * 8 * ldb);
        }
#pragma unroll
        for (int k = 0; k < 8; k++) {
            float a[8], b[8];
            *(float4*)&a[0] = *(const float4*)&As[cur][k][ty * 8];
            *(float4*)&a[4] = *(const float4*)&As[cur][k][ty * 8 + 4];
            *(float4*)&b[0] = *(const float4*)&Bs[cur][k][tx * 8];
            *(float4*)&b[4] = *(const float4*)&Bs[cur][k][tx * 8 + 4];
#pragma unroll
            for (int i = 0; i < 8; i++)
#pragma unroll
                for (int j = 0; j < 8; j++) acc[i][j] = fmaf(a[i], b[j], acc[i][j]);
        }
        if (kt + 1 < NT) {
            int nx = cur ^ 1;
            STORE_AT(nx, a2);
            *(float4*)&Bs[nx][brow][bcol] = b2;
        }
        __syncthreads();
    }

#pragma unroll
    for (int i = 0; i < 8; i++) {
        long row = m0 + ty * 8 + i;
        long off = row * ldc + n0 + tx * 8;
#pragma unroll
        for (int j = 0; j < 8; j++) {
            float v = acc[i][j];
            if (EPI == 1) v += D[off + j];
            if (EPI == 2) v += bias[n0 + tx * 8 + j];
            C[off + j] = v;
        }
    }
}

// ---------------- scores kernel: NT GEMM + scale + causal mask ----------------
// Att[h, q, t] = (sum_d Q[q,h,d] * K[t,h,d]) * scale, masked (t>q -> -1e9)
__global__ __launch_bounds__(256)
void scores_kernel(const float* __restrict__ Q, const float* __restrict__ Kx,
                   float* __restrict__ Att) {
    int h = blockIdx.z;
    const float* A = Q + h * HEAD_DIM;
    const float* B = Kx + h * HEAD_DIM;
    float* C = Att + (long)h * S_LEN * S_LEN;

    const int m0 = blockIdx.y * 128;
    const int n0 = blockIdx.x * 128;
    const int tid = threadIdx.x;
    const int ty = tid >> 4;
    const int tx = tid & 15;

    if (n0 > m0 + 127) {  // fully masked tile
#pragma unroll
        for (int i = 0; i < 8; i++) {
            long off = (long)(m0 + ty * 8 + i) * S_LEN + n0 + tx * 8;
#pragma unroll
            for (int j = 0; j < 8; j++) C[off + j] = -1e9f;
        }
        return;
    }

    __shared__ float As[2][8][128];
    __shared__ float Bs[2][8][128];
    const int arow = tid >> 1;
    const int acol = (tid & 1) * 4;

    const float* Ap = A + (long)(m0 + arow) * H_DIM + acol;
    const float* Bp = B + (long)(n0 + arow) * H_DIM + acol;

    float acc[8][8];
#pragma unroll
    for (int i = 0; i < 8; i++)
#pragma unroll
        for (int j = 0; j < 8; j++) acc[i][j] = 0.f;

    float4 av = *(const float4*)Ap;
    float4 bv = *(const float4*)Bp;
    STORE_AT(0, av);
    Bs[0][acol + 0][arow] = bv.x; Bs[0][acol + 1][arow] = bv.y;
    Bs[0][acol + 2][arow] = bv.z; Bs[0][acol + 3][arow] = bv.w;
    __syncthreads();

    const int NT = HEAD_DIM / 8;  // 16
    for (int kt = 0; kt < NT; kt++) {
        int cur = kt & 1;
        float4 a2, b2;
        if (kt + 1 < NT) {
            a2 = *(const float4*)(Ap + (kt + 1) * 8);
            b2 = *(const float4*)(Bp + (kt + 1) * 8);
        }
#pragma unroll
        for (int k = 0; k < 8; k++) {
            float a[8], b[8];
            *(float4*)&a[0] = *(const float4*)&As[cur][k][ty * 8];
            *(float4*)&a[4] = *(const float4*)&As[cur][k][ty * 8 + 4];
            *(float4*)&b[0] = *(const float4*)&Bs[cur][k][tx * 8];
            *(float4*)&b[4] = *(const float4*)&Bs[cur][k][tx * 8 + 4];
#pragma unroll
            for (int i = 0; i < 8; i++)
#pragma unroll
                for (int j = 0; j < 8; j++) acc[i][j] = fmaf(a[i], b[j], acc[i][j]);
        }
        if (kt + 1 < NT) {
            int nx = cur ^ 1;
            STORE_AT(nx, a2);
            Bs[nx][acol + 0][arow] = b2.x; Bs[nx][acol + 1][arow] = b2.y;
            Bs[nx][acol + 2][arow] = b2.z; Bs[nx][acol + 3][arow] = b2.w;
        }
        __syncthreads();
    }

    const float sc = 0.08838834764831845f;  // 1/sqrt(128)
#pragma unroll
    for (int i = 0; i < 8; i++) {
        int row = m0 + ty * 8 + i;
        long off = (long)row * S_LEN + n0 + tx * 8;
#pragma unroll
        for (int j = 0; j < 8; j++) {
            int col = n0 + tx * 8 + j;
            C[off + j] = (col <= row) ? acc[i][j] * sc : -1e9f;
        }
    }
}

// ---------------- host launch ----------------
extern "C" void kernel_launch(void* const* d_in, const int* in_sizes, int n_in,
                              void* d_out, int out_size) {
    const int*   x     = (const int*)d_in[0];
    const float* embed = (const float*)d_in[1];
    const float* Wq    = (const float*)d_in[2];
    const float* Wk    = (const float*)d_in[3];
    const float* Wv    = (const float*)d_in[4];
    const float* Wo    = (const float*)d_in[5];
    const float* Wg    = (const float*)d_in[6];
    const float* Wu    = (const float*)d_in[7];
    const float* Wd    = (const float*)d_in[8];
    const float* ln1   = (const float*)d_in[9];
    const float* ln2   = (const float*)d_in[10];
    const float* lnf   = (const float*)d_in[11];
    const float* Wout  = (const float*)d_in[12];
    const float* bout  = (const float*)d_in[13];
    float* out = (float*)d_out;

    float* ws = nullptr;
    cudaGetSymbolAddress((void**)&ws, g_ws);
    float* hb = ws + OFF_H;
    float* ab = ws + OFF_A;
    float* qb = ws + OFF_Q;
    float* kb = ws + OFF_K;
    float* vb = ws + OFF_V;
    float* ob = ws + OFF_O;
    float* gb = ws + OFF_G;
    float* ub = ws + OFF_U;
    float* att = ws + OFF_ATT;

    const dim3 blk(256);

    embed_kernel<<<(S_LEN * H_DIM) / 256, blk>>>(x, embed, hb);

    for (int l = 0; l < N_LAYERS; l++) {
        const float* wq = Wq + (long)l * H_DIM * H_DIM;
        const float* wk = Wk + (long)l * H_DIM * H_DIM;
        const float* wv = Wv + (long)l * H_DIM * H_DIM;
        const float* wo = Wo + (long)l * H_DIM * H_DIM;
        const float* wg = Wg + (long)l * H_DIM * FFN_DIM;
        const float* wu = Wu + (long)l * H_DIM * FFN_DIM;
        const float* wd = Wd + (long)l * FFN_DIM * H_DIM;

        rmsnorm_kernel<<<S_LEN, blk>>>(hb, ln1 + (long)l * H_DIM, ab);

        dim3 gQ(H_DIM / 128, S_LEN / 128, 1);
        sgemm_nn<0><<<gQ, blk>>>(S_LEN, H_DIM, H_DIM, ab, H_DIM, 0, wq, H_DIM, 0,
                                 qb, H_DIM, 0, nullptr, 0, nullptr);
        sgemm_nn<0><<<gQ, blk>>>(S_LEN, H_DIM, H_DIM, ab, H_DIM, 0, wk, H_DIM, 0,
                                 kb, H_DIM, 0, nullptr, 0, nullptr);
        sgemm_nn<0><<<gQ, blk>>>(S_LEN, H_DIM, H_DIM, ab, H_DIM, 0, wv, H_DIM, 0,
                                 vb, H_DIM, 0, nullptr, 0, nullptr);

        rope_kernel<<<(S_LEN * N_HEADS * 64) / 256, blk>>>(qb);
        rope_kernel<<<(S_LEN * N_HEADS * 64) / 256, blk>>>(kb);

        dim3 gS(S_LEN / 128, S_LEN / 128, N_HEADS);
        scores_kernel<<<gS, blk>>>(qb, kb, att);

        softmax_kernel<<<N_HEADS * S_LEN, blk>>>(att);

        dim3 gAV(1, S_LEN / 128, N_HEADS);
        sgemm_nn<0><<<gAV, blk>>>(S_LEN, HEAD_DIM, S_LEN,
                                  att, S_LEN, (long)S_LEN * S_LEN,
                                  vb, H_DIM, (long)HEAD_DIM,
                                  ob, H_DIM, (long)HEAD_DIM, nullptr, 0, nullptr);

        sgemm_nn<1><<<gQ, blk>>>(S_LEN, H_DIM, H_DIM, ob, H_DIM, 0, wo, H_DIM, 0,
                                 hb, H_DIM, 0, hb, 0, nullptr);

        rmsnorm_kernel<<<S_LEN, blk>>>(hb, ln2 + (long)l * H_DIM, ab);

        dim3 gF(FFN_DIM / 128, S_LEN / 128, 1);
        sgemm_nn<0><<<gF, blk>>>(S_LEN, FFN_DIM, H_DIM, ab, H_DIM, 0, wg, FFN_DIM, 0,
                                 gb, FFN_DIM, 0, nullptr, 0, nullptr);
        sgemm_nn<0><<<gF, blk>>>(S_LEN, FFN_DIM, H_DIM, ab, H_DIM, 0, wu, FFN_DIM, 0,
                                 ub, FFN_DIM, 0, nullptr, 0, nullptr);

        silu_mul_kernel<<<(S_LEN * (long)FFN_DIM) / 256, blk>>>(gb, ub, gb);

        sgemm_nn<1><<<gQ, blk>>>(S_LEN, H_DIM, FFN_DIM, gb, FFN_DIM, 0, wd, H_DIM, 0,
                                 hb, H_DIM, 0, hb, 0, nullptr);
    }

    rmsnorm_kernel<<<S_LEN, blk>>>(hb, lnf, ab);

    dim3 gO(OUT_DIM / 128, S_LEN / 128, 1);
    sgemm_nn<2><<<gO, blk>>>(S_LEN, OUT_DIM, H_DIM, ab, H_DIM, 0, Wout, OUT_DIM, 0,
                             out, OUT_DIM, 0, nullptr, 0, bout);
}

// round 2
// speedup vs baseline: 2.1903x; 2.1903x over previous
#include <cuda_runtime.h>
#include <cuda_bf16.h>
#include <math.h>
#include <stdint.h>

// ---------------- model dims ----------------
#define S_LEN   1024
#define H_DIM   4096
#define N_HEADS 32
#define HEAD_DIM 128
#define FFN_DIM 11008
#define N_LAYERS 2
#define OUT_DIM 512

// ---------------- workspace ----------------
#define SZ_SH  (4194304L)          // S*H
#define SZ_SF  (11272192L)         // S*F
#define SZ_ATT (33554432L)         // NH*S*S

#define OFF_H   (0L)
#define OFF_A   (1L*SZ_SH)
#define OFF_Q   (2L*SZ_SH)
#define OFF_K   (3L*SZ_SH)
#define OFF_V   (4L*SZ_SH)
#define OFF_O   (5L*SZ_SH)
#define OFF_G   (6L*SZ_SH)
#define OFF_U   (6L*SZ_SH + SZ_SF)
#define OFF_ATT (6L*SZ_SH + 2L*SZ_SF)

__device__ float g_ws[6L*4194304L + 2L*11272192L + 33554432L];

// ---------------- elementwise kernels ----------------
__global__ void embed_kernel(const int* __restrict__ x, const float* __restrict__ emb,
                             float* __restrict__ h) {
    long idx = (long)blockIdx.x * blockDim.x + threadIdx.x;  // S*H
    int s = (int)(idx >> 12);
    int j = (int)(idx & 4095);
    h[idx] = emb[(long)x[s] * H_DIM + j];
}

__global__ void rmsnorm_kernel(const float* __restrict__ in, const float* __restrict__ w,
                               float* __restrict__ out) {
    int row = blockIdx.x;
    const float4* ip = (const float4*)(in + (long)row * H_DIM);
    const float4* wp = (const float4*)w;
    float4* op = (float4*)(out + (long)row * H_DIM);
    int t = threadIdx.x;
    float ss = 0.f;
    float4 va[4];
#pragma unroll
    for (int u = 0; u < 4; u++) {
        va[u] = ip[t + u * 256];
        ss += va[u].x*va[u].x + va[u].y*va[u].y + va[u].z*va[u].z + va[u].w*va[u].w;
    }
    __shared__ float red[256];
    red[t] = ss; __syncthreads();
    for (int s2 = 128; s2 > 0; s2 >>= 1) {
        if (t < s2) red[t] += red[t + s2];
        __syncthreads();
    }
    float scale = rsqrtf(red[0] / (float)H_DIM + 1e-6f);
#pragma unroll
    for (int u = 0; u < 4; u++) {
        int i = t + u * 256;
        float4 a = va[u], ww = wp[i];
        float4 r;
        r.x = a.x * scale * ww.x; r.y = a.y * scale * ww.y;
        r.z = a.z * scale * ww.z; r.w = a.w * scale * ww.w;
        op[i] = r;
    }
}

__global__ void rope_kernel(float* __restrict__ q) {
    long idx = (long)blockIdx.x * blockDim.x + threadIdx.x;  // S*NH*64
    int i = (int)(idx & 63);
    int h = (int)((idx >> 6) & 31);
    int s = (int)(idx >> 11);
    long base = (long)s * H_DIM + h * HEAD_DIM;
    double inv = pow(10000.0, -(double)i / 64.0);
    double ang = (double)s * inv;
    float c = (float)cos(ang), sn = (float)sin(ang);
    float x1 = q[base + i], x2 = q[base + i + 64];
    q[base + i]      = x1 * c - x2 * sn;
    q[base + i + 64] = x2 * c + x1 * sn;
}

__global__ void softmax_kernel(float* __restrict__ att) {
    long row = blockIdx.x;  // NH*S rows of length S
    float4* p4 = (float4*)(att + row * (long)S_LEN);
    int t = threadIdx.x;
    float4 a = p4[t];
    float m = fmaxf(fmaxf(a.x, a.y), fmaxf(a.z, a.w));
    __shared__ float red[256];
    red[t] = m; __syncthreads();
    for (int s2 = 128; s2 > 0; s2 >>= 1) {
        if (t < s2) red[t] = fmaxf(red[t], red[t + s2]);
        __syncthreads();
    }
    m = red[0];
    __syncthreads();
    a.x = expf(a.x - m); a.y = expf(a.y - m);
    a.z = expf(a.z - m); a.w = expf(a.w - m);
    red[t] = a.x + a.y + a.z + a.w; __syncthreads();
    for (int s2 = 128; s2 > 0; s2 >>= 1) {
        if (t < s2) red[t] += red[t + s2];
        __syncthreads();
    }
    float inv = 1.0f / red[0];
    a.x *= inv; a.y *= inv; a.z *= inv; a.w *= inv;
    p4[t] = a;
}

__global__ void silu_mul_kernel(const float* __restrict__ g, const float* __restrict__ u,
                                float* __restrict__ out) {
    long idx = (long)blockIdx.x * blockDim.x + threadIdx.x;  // S*F
    float x = g[idx];
    float s = x / (1.0f + expf(-x));
    out[idx] = s * u[idx];
}

// ================= bf16-split tensor-core GEMM =================
// C[M,N] = A[M,K] * B[K,N]  (row-major fp32 in gmem), computed as
// Ahi*Bhi + Ahi*Blo + Alo*Bhi with hi/lo bf16 split, fp32 accumulate.
// CTA tile 128x128, K-tile 32, 256 threads (2x4 warps, warp tile 64x32).

#define APITCH 40   // bf16 elems per A smem row (32 + pad), 80B pitch
#define BPITCH 136  // bf16 elems per B smem row (128 + pad), 272B pitch
#define HSMEM_BYTES (2*((2*128*APITCH) + (2*32*BPITCH)) * 2)

__device__ __forceinline__ uint32_t smem_u32(const void* p) {
    return (uint32_t)__cvta_generic_to_shared(p);
}
__device__ __forceinline__ void ldsm4(uint32_t a, uint32_t* r) {
    asm volatile("ldmatrix.sync.aligned.m8n8.x4.shared.b16 {%0,%1,%2,%3}, [%4];"
        : "=r"(r[0]), "=r"(r[1]), "=r"(r[2]), "=r"(r[3]) : "r"(a));
}
__device__ __forceinline__ void ldsm4t(uint32_t a, uint32_t* r) {
    asm volatile("ldmatrix.sync.aligned.m8n8.x4.trans.shared.b16 {%0,%1,%2,%3}, [%4];"
        : "=r"(r[0]), "=r"(r[1]), "=r"(r[2]), "=r"(r[3]) : "r"(a));
}
__device__ __forceinline__ void mma16816(float* c, const uint32_t* a, uint32_t b0, uint32_t b1) {
    asm volatile("mma.sync.aligned.m16n8k16.row.col.f32.bf16.bf16.f32 "
        "{%0,%1,%2,%3}, {%4,%5,%6,%7}, {%8,%9}, {%0,%1,%2,%3};"
        : "+f"(c[0]), "+f"(c[1]), "+f"(c[2]), "+f"(c[3])
        : "r"(a[0]), "r"(a[1]), "r"(a[2]), "r"(a[3]), "r"(b0), "r"(b1));
}
__device__ __forceinline__ uint32_t pack_bf2(__nv_bfloat16 a, __nv_bfloat16 b) {
    __nv_bfloat162 t = __halves2bfloat162(a, b);
    return *reinterpret_cast<uint32_t*>(&t);
}
__device__ __forceinline__ void split4(float4 v, uint2& hi, uint2& lo) {
    __nv_bfloat16 h0 = __float2bfloat16_rn(v.x), h1 = __float2bfloat16_rn(v.y);
    __nv_bfloat16 h2 = __float2bfloat16_rn(v.z), h3 = __float2bfloat16_rn(v.w);
    __nv_bfloat16 l0 = __float2bfloat16_rn(v.x - __bfloat162float(h0));
    __nv_bfloat16 l1 = __float2bfloat16_rn(v.y - __bfloat162float(h1));
    __nv_bfloat16 l2 = __float2bfloat16_rn(v.z - __bfloat162float(h2));
    __nv_bfloat16 l3 = __float2bfloat16_rn(v.w - __bfloat162float(h3));
    hi = make_uint2(pack_bf2(h0, h1), pack_bf2(h2, h3));
    lo = make_uint2(pack_bf2(l0, l1), pack_bf2(l2, l3));
}

// EPI: 0 = C=AB ; 1 = C=AB+D ; 2 = C=AB+bias[n]
template <int EPI>
__global__ __launch_bounds__(256)
void hgemm_split(int M, int N, int K,
                 const float* __restrict__ A, int lda,
                 const float* __restrict__ B, int ldb,
                 float* __restrict__ C, int ldc,
                 const float* __restrict__ D,
                 const float* __restrict__ bias) {
    extern __shared__ char smraw[];
    __nv_bfloat16* AsHi = (__nv_bfloat16*)smraw;               // [2][128][APITCH]
    __nv_bfloat16* AsLo = AsHi + 2 * 128 * APITCH;
    __nv_bfloat16* BsHi = AsLo + 2 * 128 * APITCH;             // [2][32][BPITCH]
    __nv_bfloat16* BsLo = BsHi + 2 * 32 * BPITCH;

    const int tid = threadIdx.x;
    const int lane = tid & 31, warp = tid >> 5;
    const int wm = warp >> 2, wn = warp & 3;       // 2 x 4 warps
    const int m0 = blockIdx.y * 128, n0 = blockIdx.x * 128;

    float c[4][4][4];
#pragma unroll
    for (int i = 0; i < 4; i++)
#pragma unroll
        for (int j = 0; j < 4; j++)
#pragma unroll
            for (int k = 0; k < 4; k++) c[i][j][k] = 0.f;

    // load coords: A tile 128x32 fp32 (4 float4/thread), B tile 32x128 (4 float4/thread)
    const int arow = tid >> 3, ak = (tid & 7) * 4;
    const int bk = tid >> 5, bn = (tid & 31) * 4;
    const float* Ap = A + (long)(m0 + arow) * lda + ak;
    const float* Bp = B + (long)bk * ldb + n0 + bn;

    float4 fa[4], fb[4];

    auto fetch = [&](int kt) {
        const float* a = Ap + kt * 32;
        const float* b = Bp + (long)kt * 32 * ldb;
#pragma unroll
        for (int it = 0; it < 4; it++) {
            fa[it] = *(const float4*)(a + (long)it * 32 * lda);
            fb[it] = *(const float4*)(b + (long)it * 8 * ldb);
        }
    };
    auto store_stage = [&](int s) {
#pragma unroll
        for (int it = 0; it < 4; it++) {
            uint2 hi, lo;
            split4(fa[it], hi, lo);
            int aoff = (s * 128 + arow + it * 32) * APITCH + ak;
            *(uint2*)(AsHi + aoff) = hi;
            *(uint2*)(AsLo + aoff) = lo;
            split4(fb[it], hi, lo);
            int boff = (s * 32 + bk + it * 8) * BPITCH + bn;
            *(uint2*)(BsHi + boff) = hi;
            *(uint2*)(BsLo + boff) = lo;
        }
    };
    auto mma_stage = [&](int s) {
#pragma unroll
        for (int ks = 0; ks < 32; ks += 16) {
            uint32_t ah[4][4], al[4][4], bh[2][4], bl[2][4];
#pragma unroll
            for (int mi = 0; mi < 4; mi++) {
                int row = s * 128 + wm * 64 + mi * 16 + (lane & 15);
                int col = ks + (lane >> 4) * 8;
                ldsm4(smem_u32(AsHi + row * APITCH + col), ah[mi]);
                ldsm4(smem_u32(AsLo + row * APITCH + col), al[mi]);
            }
#pragma unroll
            for (int nh = 0; nh < 2; nh++) {
                int row = s * 32 + ks + (lane & 15);
                int col = wn * 32 + nh * 16 + (lane >> 4) * 8;
                ldsm4t(smem_u32(BsHi + row * BPITCH + col), bh[nh]);
                ldsm4t(smem_u32(BsLo + row * BPITCH + col), bl[nh]);
            }
#pragma unroll
            for (int mi = 0; mi < 4; mi++)
#pragma unroll
                for (int ni = 0; ni < 4; ni++) {
                    uint32_t b0h = bh[ni >> 1][(ni & 1) * 2], b1h = bh[ni >> 1][(ni & 1) * 2 + 1];
                    uint32_t b0l = bl[ni >> 1][(ni & 1) * 2], b1l = bl[ni >> 1][(ni & 1) * 2 + 1];
                    mma16816(c[mi][ni], ah[mi], b0h, b1h);
                    mma16816(c[mi][ni], ah[mi], b0l, b1l);
                    mma16816(c[mi][ni], al[mi], b0h, b1h);
                }
        }
    };

    const int T = K / 32;
    fetch(0);
    store_stage(0);
    __syncthreads();
    for (int t = 0; t < T; t++) {
        int cur = t & 1;
        if (t + 1 < T) fetch(t + 1);
        mma_stage(cur);
        if (t + 1 < T) {
            __syncthreads();
            store_stage(cur ^ 1);
            __syncthreads();
        }
    }

    // epilogue
#pragma unroll
    for (int mi = 0; mi < 4; mi++)
#pragma unroll
        for (int ni = 0; ni < 4; ni++) {
            int r = m0 + wm * 64 + mi * 16 + (lane >> 2);
            int col = n0 + wn * 32 + ni * 8 + (lane & 3) * 2;
            float2 v0 = make_float2(c[mi][ni][0], c[mi][ni][1]);
            float2 v1 = make_float2(c[mi][ni][2], c[mi][ni][3]);
            long o0 = (long)r * ldc + col;
            long o1 = (long)(r + 8) * ldc + col;
            if (EPI == 1) {
                float2 d0 = *(const float2*)(D + o0);
                float2 d1 = *(const float2*)(D + o1);
                v0.x += d0.x; v0.y += d0.y; v1.x += d1.x; v1.y += d1.y;
            }
            if (EPI == 2) {
                float2 bb = *(const float2*)(bias + col);
                v0.x += bb.x; v0.y += bb.y; v1.x += bb.x; v1.y += bb.y;
            }
            *(float2*)(C + o0) = v0;
            *(float2*)(C + o1) = v1;
        }
}

// ---------------- fp32 SGEMM (kept for att @ V) ----------------
#define STORE_AT(buf, v) do { As[buf][acol+0][arow]=(v).x; As[buf][acol+1][arow]=(v).y; \
                              As[buf][acol+2][arow]=(v).z; As[buf][acol+3][arow]=(v).w; } while(0)

template <int EPI>
__global__ __launch_bounds__(256)
void sgemm_nn(int M, int N, int K,
              const float* __restrict__ A, int lda, long batA,
              const float* __restrict__ B, int ldb, long batB,
              float* __restrict__ C, int ldc, long batC,
              const float* __restrict__ D, long batD,
              const float* __restrict__ bias) {
    int bz = blockIdx.z;
    A += (long)bz * batA; B += (long)bz * batB; C += (long)bz * batC;
    if (EPI == 1) D += (long)bz * batD;

    const int m0 = blockIdx.y * 128;
    const int n0 = blockIdx.x * 128;
    const int tid = threadIdx.x;

    __shared__ float As[2][8][128];
    __shared__ float Bs[2][8][128];

    const int arow = tid >> 1;
    const int acol = (tid & 1) * 4;
    const int brow = tid >> 5;
    const int bcol = (tid & 31) * 4;
    const int ty = tid >> 4;
    const int tx = tid & 15;

    float acc[8][8];
#pragma unroll
    for (int i = 0; i < 8; i++)
#pragma unroll
        for (int j = 0; j < 8; j++) acc[i][j] = 0.f;

    const float* Ap = A + (long)(m0 + arow) * lda + acol;
    const float* Bp = B + (long)brow * ldb + n0 + bcol;

    const int NT = K / 8;
    float4 av = *(const float4*)Ap;
    float4 bv = *(const float4*)Bp;
    STORE_AT(0, av);
    *(float4*)&Bs[0][brow][bcol] = bv;
    __syncthreads();

    for (int kt = 0; kt < NT; kt++) {
        int cur = kt & 1;
        float4 a2, b2;
        if (kt + 1 < NT) {
            a2 = *(const float4*)(Ap + (kt + 1) * 8);
            b2 = *(const float4*)(Bp + (long)(kt + 1) * 8 * ldb);
        }
#pragma unroll
        for (int k = 0; k < 8; k++) {
            float a[8], b[8];
            *(float4*)&a[0] = *(const float4*)&As[cur][k][ty * 8];
            *(float4*)&a[4] = *(const float4*)&As[cur][k][ty * 8 + 4];
            *(float4*)&b[0] = *(const float4*)&Bs[cur][k][tx * 8];
            *(float4*)&b[4] = *(const float4*)&Bs[cur][k][tx * 8 + 4];
#pragma unroll
            for (int i = 0; i < 8; i++)
#pragma unroll
                for (int j = 0; j < 8; j++) acc[i][j] = fmaf(a[i], b[j], acc[i][j]);
        }
        if (kt + 1 < NT) {
            int nx = cur ^ 1;
            STORE_AT(nx, a2);
            *(float4*)&Bs[nx][brow][bcol] = b2;
        }
        __syncthreads();
    }

#pragma unroll
    for (int i = 0; i < 8; i++) {
        long row = m0 + ty * 8 + i;
        long off = row * ldc + n0 + tx * 8;
#pragma unroll
        for (int j = 0; j < 8; j++) {
            float v = acc[i][j];
            if (EPI == 1) v += D[off + j];
            if (EPI == 2) v += bias[n0 + tx * 8 + j];
            C[off + j] = v;
        }
    }
}

// ---------------- scores kernel: NT GEMM + scale + causal mask ----------------
__global__ __launch_bounds__(256)
void scores_kernel(const float* __restrict__ Q, const float* __restrict__ Kx,
                   float* __restrict__ Att) {
    int h = blockIdx.z;
    const float* A = Q + h * HEAD_DIM;
    const float* B = Kx + h * HEAD_DIM;
    float* C = Att + (long)h * S_LEN * S_LEN;

    const int m0 = blockIdx.y * 128;
    const int n0 = blockIdx.x * 128;
    const int tid = threadIdx.x;
    const int ty = tid >> 4;
    const int tx = tid & 15;

    if (n0 > m0 + 127) {  // fully masked tile
#pragma unroll
        for (int i = 0; i < 8; i++) {
            long off = (long)(m0 + ty * 8 + i) * S_LEN + n0 + tx * 8;
#pragma unroll
            for (int j = 0; j < 8; j++) C[off + j] = -1e9f;
        }
        return;
    }

    __shared__ float As[2][8][128];
    __shared__ float Bs[2][8][128];
    const int arow = tid >> 1;
    const int acol = (tid & 1) * 4;

    const float* Ap = A + (long)(m0 + arow) * H_DIM + acol;
    const float* Bp = B + (long)(n0 + arow) * H_DIM + acol;

    float acc[8][8];
#pragma unroll
    for (int i = 0; i < 8; i++)
#pragma unroll
        for (int j = 0; j < 8; j++) acc[i][j] = 0.f;

    float4 av = *(const float4*)Ap;
    float4 bv = *(const float4*)Bp;
    STORE_AT(0, av);
    Bs[0][acol + 0][arow] = bv.x; Bs[0][acol + 1][arow] = bv.y;
    Bs[0][acol + 2][arow] = bv.z; Bs[0][acol + 3][arow] = bv.w;
    __syncthreads();

    const int NT = HEAD_DIM / 8;  // 16
    for (int kt = 0; kt < NT; kt++) {
        int cur = kt & 1;
        float4 a2, b2;
        if (kt + 1 < NT) {
            a2 = *(const float4*)(Ap + (kt + 1) * 8);
            b2 = *(const float4*)(Bp + (kt + 1) * 8);
        }
#pragma unroll
        for (int k = 0; k < 8; k++) {
            float a[8], b[8];
            *(float4*)&a[0] = *(const float4*)&As[cur][k][ty * 8];
            *(float4*)&a[4] = *(const float4*)&As[cur][k][ty * 8 + 4];
            *(float4*)&b[0] = *(const float4*)&Bs[cur][k][tx * 8];
            *(float4*)&b[4] = *(const float4*)&Bs[cur][k][tx * 8 + 4];
#pragma unroll
            for (int i = 0; i < 8; i++)
#pragma unroll
                for (int j = 0; j < 8; j++) acc[i][j] = fmaf(a[i], b[j], acc[i][j]);
        }
        if (kt + 1 < NT) {
            int nx = cur ^ 1;
            STORE_AT(nx, a2);
            Bs[nx][acol + 0][arow] = b2.x; Bs[nx][acol + 1][arow] = b2.y;
            Bs[nx][acol + 2][arow] = b2.z; Bs[nx][acol + 3][arow] = b2.w;
        }
        __syncthreads();
    }

    const float sc = 0.08838834764831845f;  // 1/sqrt(128)
#pragma unroll
    for (int i = 0; i < 8; i++) {
        int row = m0 + ty * 8 + i;
        long off = (long)row * S_LEN + n0 + tx * 8;
#pragma unroll
        for (int j = 0; j < 8; j++) {
            int col = n0 + tx * 8 + j;
            C[off + j] = (col <= row) ? acc[i][j] * sc : -1e9f;
        }
    }
}

// ---------------- host launch ----------------
extern "C" void kernel_launch(void* const* d_in, const int* in_sizes, int n_in,
                              void* d_out, int out_size) {
    const int*   x     = (const int*)d_in[0];
    const float* embed = (const float*)d_in[1];
    const float* Wq    = (const float*)d_in[2];
    const float* Wk    = (const float*)d_in[3];
    const float* Wv    = (const float*)d_in[4];
    const float* Wo    = (const float*)d_in[5];
    const float* Wg    = (const float*)d_in[6];
    const float* Wu    = (const float*)d_in[7];
    const float* Wd    = (const float*)d_in[8];
    const float* ln1   = (const float*)d_in[9];
    const float* ln2   = (const float*)d_in[10];
    const float* lnf   = (const float*)d_in[11];
    const float* Wout  = (const float*)d_in[12];
    const float* bout  = (const float*)d_in[13];
    float* out = (float*)d_out;

    float* ws = nullptr;
    cudaGetSymbolAddress((void**)&ws, g_ws);
    float* hb = ws + OFF_H;
    float* ab = ws + OFF_A;
    float* qb = ws + OFF_Q;
    float* kb = ws + OFF_K;
    float* vb = ws + OFF_V;
    float* ob = ws + OFF_O;
    float* gb = ws + OFF_G;
    float* ub = ws + OFF_U;
    float* att = ws + OFF_ATT;

    cudaFuncSetAttribute(hgemm_split<0>, cudaFuncAttributeMaxDynamicSharedMemorySize, HSMEM_BYTES);
    cudaFuncSetAttribute(hgemm_split<1>, cudaFuncAttributeMaxDynamicSharedMemorySize, HSMEM_BYTES);
    cudaFuncSetAttribute(hgemm_split<2>, cudaFuncAttributeMaxDynamicSharedMemorySize, HSMEM_BYTES);

    const dim3 blk(256);

    embed_kernel<<<(S_LEN * H_DIM) / 256, blk>>>(x, embed, hb);

    for (int l = 0; l < N_LAYERS; l++) {
        const float* wq = Wq + (long)l * H_DIM * H_DIM;
        const float* wk = Wk + (long)l * H_DIM * H_DIM;
        const float* wv = Wv + (long)l * H_DIM * H_DIM;
        const float* wo = Wo + (long)l * H_DIM * H_DIM;
        const float* wg = Wg + (long)l * H_DIM * FFN_DIM;
        const float* wu = Wu + (long)l * H_DIM * FFN_DIM;
        const float* wd = Wd + (long)l * FFN_DIM * H_DIM;

        rmsnorm_kernel<<<S_LEN, blk>>>(hb, ln1 + (long)l * H_DIM, ab);

        dim3 gQ(H_DIM / 128, S_LEN / 128);
        hgemm_split<0><<<gQ, blk, HSMEM_BYTES>>>(S_LEN, H_DIM, H_DIM, ab, H_DIM,
                                                 wq, H_DIM, qb, H_DIM, nullptr, nullptr);
        hgemm_split<0><<<gQ, blk, HSMEM_BYTES>>>(S_LEN, H_DIM, H_DIM, ab, H_DIM,
                                                 wk, H_DIM, kb, H_DIM, nullptr, nullptr);
        hgemm_split<0><<<gQ, blk, HSMEM_BYTES>>>(S_LEN, H_DIM, H_DIM, ab, H_DIM,
                                                 wv, H_DIM, vb, H_DIM, nullptr, nullptr);

        rope_kernel<<<(S_LEN * N_HEADS * 64) / 256, blk>>>(qb);
        rope_kernel<<<(S_LEN * N_HEADS * 64) / 256, blk>>>(kb);

        dim3 gS(S_LEN / 128, S_LEN / 128, N_HEADS);
        scores_kernel<<<gS, blk>>>(qb, kb, att);

        softmax_kernel<<<N_HEADS * S_LEN, blk>>>(att);

        dim3 gAV(1, S_LEN / 128, N_HEADS);
        sgemm_nn<0><<<gAV, blk>>>(S_LEN, HEAD_DIM, S_LEN,
                                  att, S_LEN, (long)S_LEN * S_LEN,
                                  vb, H_DIM, (long)HEAD_DIM,
                                  ob, H_DIM, (long)HEAD_DIM, nullptr, 0, nullptr);

        hgemm_split<1><<<gQ, blk, HSMEM_BYTES>>>(S_LEN, H_DIM, H_DIM, ob, H_DIM,
                                                 wo, H_DIM, hb, H_DIM, hb, nullptr);

        rmsnorm_kernel<<<S_LEN, blk>>>(hb, ln2 + (long)l * H_DIM, ab);

        dim3 gF(FFN_DIM / 128, S_LEN / 128);
        hgemm_split<0><<<gF, blk, HSMEM_BYTES>>>(S_LEN, FFN_DIM, H_DIM, ab, H_DIM,
                                                 wg, FFN_DIM, gb, FFN_DIM, nullptr, nullptr);
        hgemm_split<0><<<gF, blk, HSMEM_BYTES>>>(S_LEN, FFN_DIM, H_DIM, ab, H_DIM,
                                                 wu, FFN_DIM, ub, FFN_DIM, nullptr, nullptr);

        silu_mul_kernel<<<(S_LEN * (long)FFN_DIM) / 256, blk>>>(gb, ub, gb);

        hgemm_split<1><<<gQ, blk, HSMEM_BYTES>>>(S_LEN, H_DIM, FFN_DIM, gb, FFN_DIM,
                                                 wd, H_DIM, hb, H_DIM, hb, nullptr);
    }

    rmsnorm_kernel<<<S_LEN, blk>>>(hb, lnf, ab);

    dim3 gO(OUT_DIM / 128, S_LEN / 128);
    hgemm_split<2><<<gO, blk, HSMEM_BYTES>>>(S_LEN, OUT_DIM, H_DIM, ab, H_DIM,
                                             Wout, OUT_DIM, out, OUT_DIM, nullptr, bout);
}

// round 4
// speedup vs baseline: 2.3759x; 1.0847x over previous
#include <cuda_runtime.h>
#include <cuda_bf16.h>
#include <math.h>
#include <stdint.h>

// ---------------- model dims ----------------
#define S_LEN   1024
#define H_DIM   4096
#define N_HEADS 32
#define HEAD_DIM 128
#define FFN_DIM 11008
#define N_LAYERS 2
#define OUT_DIM 512

// ---------------- workspace ----------------
#define SZ_SH  (4194304L)          // S*H
#define SZ_SF  (11272192L)         // S*F
#define SZ_ATT (33554432L)         // NH*S*S

#define OFF_H   (0L)
#define OFF_A   (1L*SZ_SH)
#define OFF_Q   (2L*SZ_SH)
#define OFF_K   (3L*SZ_SH)
#define OFF_V   (4L*SZ_SH)
#define OFF_O   (5L*SZ_SH)
#define OFF_G   (6L*SZ_SH)
#define OFF_U   (6L*SZ_SH + SZ_SF)
#define OFF_ATT (6L*SZ_SH + 2L*SZ_SF)

__device__ float g_ws[6L*4194304L + 2L*11272192L + 33554432L];

// bf16 split scratch: activations (up to S*F) and weights (up to H*F)
__device__ __nv_bfloat16 g_ahi[11272192L];
__device__ __nv_bfloat16 g_alo[11272192L];
__device__ __nv_bfloat16 g_bhi[45088768L];
__device__ __nv_bfloat16 g_blo[45088768L];

// ---------------- elementwise kernels ----------------
__global__ void embed_kernel(const int* __restrict__ x, const float* __restrict__ emb,
                             float* __restrict__ h) {
    long idx = (long)blockIdx.x * blockDim.x + threadIdx.x;  // S*H
    int s = (int)(idx >> 12);
    int j = (int)(idx & 4095);
    h[idx] = emb[(long)x[s] * H_DIM + j];
}

__global__ void rmsnorm_kernel(const float* __restrict__ in, const float* __restrict__ w,
                               float* __restrict__ out) {
    int row = blockIdx.x;
    const float4* ip = (const float4*)(in + (long)row * H_DIM);
    const float4* wp = (const float4*)w;
    float4* op = (float4*)(out + (long)row * H_DIM);
    int t = threadIdx.x;
    float ss = 0.f;
    float4 va[4];
#pragma unroll
    for (int u = 0; u < 4; u++) {
        va[u] = ip[t + u * 256];
        ss += va[u].x*va[u].x + va[u].y*va[u].y + va[u].z*va[u].z + va[u].w*va[u].w;
    }
    __shared__ float red[256];
    red[t] = ss; __syncthreads();
    for (int s2 = 128; s2 > 0; s2 >>= 1) {
        if (t < s2) red[t] += red[t + s2];
        __syncthreads();
    }
    float scale = rsqrtf(red[0] / (float)H_DIM + 1e-6f);
#pragma unroll
    for (int u = 0; u < 4; u++) {
        int i = t + u * 256;
        float4 a = va[u], ww = wp[i];
        float4 r;
        r.x = a.x * scale * ww.x; r.y = a.y * scale * ww.y;
        r.z = a.z * scale * ww.z; r.w = a.w * scale * ww.w;
        op[i] = r;
    }
}

__global__ void rope_kernel(float* __restrict__ q) {
    long idx = (long)blockIdx.x * blockDim.x + threadIdx.x;  // S*NH*64
    int i = (int)(idx & 63);
    int h = (int)((idx >> 6) & 31);
    int s = (int)(idx >> 11);
    long base = (long)s * H_DIM + h * HEAD_DIM;
    double inv = pow(10000.0, -(double)i / 64.0);
    double ang = (double)s * inv;
    float c = (float)cos(ang), sn = (float)sin(ang);
    float x1 = q[base + i], x2 = q[base + i + 64];
    q[base + i]      = x1 * c - x2 * sn;
    q[base + i + 64] = x2 * c + x1 * sn;
}

__global__ void softmax_kernel(float* __restrict__ att) {
    long row = blockIdx.x;  // NH*S rows of length S
    float4* p4 = (float4*)(att + row * (long)S_LEN);
    int t = threadIdx.x;
    float4 a = p4[t];
    float m = fmaxf(fmaxf(a.x, a.y), fmaxf(a.z, a.w));
    __shared__ float red[256];
    red[t] = m; __syncthreads();
    for (int s2 = 128; s2 > 0; s2 >>= 1) {
        if (t < s2) red[t] = fmaxf(red[t], red[t + s2]);
        __syncthreads();
    }
    m = red[0];
    __syncthreads();
    a.x = expf(a.x - m); a.y = expf(a.y - m);
    a.z = expf(a.z - m); a.w = expf(a.w - m);
    red[t] = a.x + a.y + a.z + a.w; __syncthreads();
    for (int s2 = 128; s2 > 0; s2 >>= 1) {
        if (t < s2) red[t] += red[t + s2];
        __syncthreads();
    }
    float inv = 1.0f / red[0];
    a.x *= inv; a.y *= inv; a.z *= inv; a.w *= inv;
    p4[t] = a;
}

__global__ void silu_mul_kernel(const float* __restrict__ g, const float* __restrict__ u,
                                float* __restrict__ out) {
    long idx = (long)blockIdx.x * blockDim.x + threadIdx.x;  // S*F
    float x = g[idx];
    float s = x / (1.0f + expf(-x));
    out[idx] = s * u[idx];
}

// ---------------- fp32 -> bf16 hi/lo split ----------------
__global__ void split_kernel(const float* __restrict__ in,
                             __nv_bfloat16* __restrict__ hi,
                             __nv_bfloat16* __restrict__ lo, long n4) {
    long i = (long)blockIdx.x * blockDim.x + threadIdx.x;
    if (i >= n4) return;
    float4 v = ((const float4*)in)[i];
    __nv_bfloat16 h0 = __float2bfloat16_rn(v.x), h1 = __float2bfloat16_rn(v.y);
    __nv_bfloat16 h2 = __float2bfloat16_rn(v.z), h3 = __float2bfloat16_rn(v.w);
    __nv_bfloat16 l0 = __float2bfloat16_rn(v.x - __bfloat162float(h0));
    __nv_bfloat16 l1 = __float2bfloat16_rn(v.y - __bfloat162float(h1));
    __nv_bfloat16 l2 = __float2bfloat16_rn(v.z - __bfloat162float(h2));
    __nv_bfloat16 l3 = __float2bfloat16_rn(v.w - __bfloat162float(h3));
    __nv_bfloat162 ha = __halves2bfloat162(h0, h1), hb = __halves2bfloat162(h2, h3);
    __nv_bfloat162 la = __halves2bfloat162(l0, l1), lb = __halves2bfloat162(l2, l3);
    ((uint2*)hi)[i] = make_uint2(*(uint32_t*)&ha, *(uint32_t*)&hb);
    ((uint2*)lo)[i] = make_uint2(*(uint32_t*)&la, *(uint32_t*)&lb);
}

// ================= bf16-split HMMA GEMM with cp.async pipeline =================
// C[M,N] fp32 = Ahi*Bhi + Ahi*Blo + Alo*Bhi, operands pre-split bf16 in gmem.
// CTA tile 128x128, K-tile 32, 256 threads (2x4 warps, warp tile 64x32),
// 4-stage cp.async pipeline. SMEM/stage: A[128 rows][hi 64B | lo 64B] swizzled (16KB),
// Bhi[32][256B] + Blo[32][256B] swizzled (16KB).

#define BSTAGE 32768
#define BG_SMEM (4 * BSTAGE)

__device__ __forceinline__ uint32_t smem_u32(const void* p) {
    return (uint32_t)__cvta_generic_to_shared(p);
}
__device__ __forceinline__ void cp16(uint32_t dst, const void* src) {
    asm volatile("cp.async.cg.shared.global [%0], [%1], 16;" :: "r"(dst), "l"(src));
}
__device__ __forceinline__ void ldsm4(uint32_t a, uint32_t* r) {
    asm volatile("ldmatrix.sync.aligned.m8n8.x4.shared.b16 {%0,%1,%2,%3}, [%4];"
        : "=r"(r[0]), "=r"(r[1]), "=r"(r[2]), "=r"(r[3]) : "r"(a));
}
__device__ __forceinline__ void ldsm4t(uint32_t a, uint32_t* r) {
    asm volatile("ldmatrix.sync.aligned.m8n8.x4.trans.shared.b16 {%0,%1,%2,%3}, [%4];"
        : "=r"(r[0]), "=r"(r[1]), "=r"(r[2]), "=r"(r[3]) : "r"(a));
}
__device__ __forceinline__ void mma16816(float* c, const uint32_t* a, uint32_t b0, uint32_t b1) {
    asm volatile("mma.sync.aligned.m16n8k16.row.col.f32.bf16.bf16.f32 "
        "{%0,%1,%2,%3}, {%4,%5,%6,%7}, {%8,%9}, {%0,%1,%2,%3};"
        : "+f"(c[0]), "+f"(c[1]), "+f"(c[2]), "+f"(c[3])
        : "r"(a[0]), "r"(a[1]), "r"(a[2]), "r"(a[3]), "r"(b0), "r"(b1));
}

// EPI: 0 = C=AB ; 1 = C=AB+D ; 2 = C=AB+bias[n]
template <int EPI>
__global__ __launch_bounds__(256, 1)
void bgemm(int K,
           const __nv_bfloat16* __restrict__ Ahi, const __nv_bfloat16* __restrict__ Alo,
           const __nv_bfloat16* __restrict__ Bhi, const __nv_bfloat16* __restrict__ Blo,
           int ldb,
           float* __restrict__ C, int ldc,
           const float* __restrict__ D,
           const float* __restrict__ bias) {
    extern __shared__ char sm[];
    uint32_t smb = smem_u32(sm);
    const int tid = threadIdx.x;
    const int lane = tid & 31, warp = tid >> 5;
    const int wm = warp >> 2, wn = warp & 3;       // 2 x 4 warps
    const int m0 = blockIdx.y * 128, n0 = blockIdx.x * 128;
    const int lda = K;

    float c[4][4][4];
#pragma unroll
    for (int i = 0; i < 4; i++)
#pragma unroll
        for (int j = 0; j < 4; j++)
#pragma unroll
            for (int k = 0; k < 4; k++) c[i][j][k] = 0.f;

    auto load_stage = [&](int s, int kt) {
        uint32_t sa = smb + s * BSTAGE;
        uint32_t sb = smb + s * BSTAGE + 16384;
        // A: 1024 16B-chunks (hi: sub 0-3, lo: sub 4-7)
#pragma unroll
        for (int i = 0; i < 4; i++) {
            int cidx = tid + i * 256;
            int row = cidx >> 3, sub = cidx & 7;
            int ci = sub & 3;
            const __nv_bfloat16* g = ((sub < 4) ? Ahi : Alo)
                                     + (long)(m0 + row) * lda + kt * 32 + ci * 8;
            uint32_t inner = ((sub < 4) ? 0u : 64u) + ci * 16;
            cp16(sa + row * 128 + (inner ^ ((row & 7) << 4)), g);
        }
        // B: 1024 chunks (hi: first 512, lo: next 512)
#pragma unroll
        for (int i = 0; i < 4; i++) {
            int cidx = tid + i * 256;
            int arr = cidx >> 9;
            int within = cidx & 511;
            int row = within >> 4, ci = within & 15;
            const __nv_bfloat16* g = (arr ? Blo : Bhi)
                                     + (long)(kt * 32 + row) * ldb + n0 + ci * 8;
            uint32_t dst = sb + arr * 8192 + row * 256 + ((ci * 16) ^ ((row & 7) << 4));
            cp16(dst, g);
        }
    };

    auto mma_stage = [&](int s) {
        uint32_t sa = smb + s * BSTAGE;
        uint32_t sb = smb + s * BSTAGE + 16384;
#pragma unroll
        for (int ks = 0; ks < 2; ks++) {
            uint32_t ah[4][4], al[4][4], bh[2][4], bl[2][4];
#pragma unroll
            for (int mi = 0; mi < 4; mi++) {
                int row = wm * 64 + mi * 16 + (lane & 15);
                uint32_t innh = ks * 32 + (lane >> 4) * 16;
                uint32_t swz = (row & 7) << 4;
                uint32_t rb = sa + row * 128;
                ldsm4(rb + (innh ^ swz), ah[mi]);
                ldsm4(rb + ((innh + 64) ^ swz), al[mi]);
            }
#pragma unroll
            for (int nh = 0; nh < 2; nh++) {
                int k = ks * 16 + (lane & 15);
                uint32_t inn = wn * 64 + nh * 32 + (lane >> 4) * 16;
                uint32_t off = k * 256 + ((inn) ^ ((k & 7) << 4));
                ldsm4t(sb + off, bh[nh]);
                ldsm4t(sb + 8192 + off, bl[nh]);
            }
#pragma unroll
            for (int mi = 0; mi < 4; mi++)
#pragma unroll
                for (int ni = 0; ni < 4; ni++)
                    mma16816(c[mi][ni], ah[mi],
                             bh[ni >> 1][(ni & 1) * 2], bh[ni >> 1][(ni & 1) * 2 + 1]);
#pragma unroll
            for (int mi = 0; mi < 4; mi++)
#pragma unroll
                for (int ni = 0; ni < 4; ni++)
                    mma16816(c[mi][ni], ah[mi],
                             bl[ni >> 1][(ni & 1) * 2], bl[ni >> 1][(ni & 1) * 2 + 1]);
#pragma unroll
            for (int mi = 0; mi < 4; mi++)
#pragma unroll
                for (int ni = 0; ni < 4; ni++)
                    mma16816(c[mi][ni], al[mi],
                             bh[ni >> 1][(ni & 1) * 2], bh[ni >> 1][(ni & 1) * 2 + 1]);
        }
    };

    const int T = K / 32;
    // prefetch 3 stages
    for (int s = 0; s < 3; s++) {
        if (s < T) load_stage(s, s);
        asm volatile("cp.async.commit_group;");
    }
    for (int kt = 0; kt < T; kt++) {
        asm volatile("cp.async.wait_group 2;");
        __syncthreads();
        mma_stage(kt & 3);
        __syncthreads();
        if (kt + 3 < T) load_stage((kt + 3) & 3, kt + 3);
        asm volatile("cp.async.commit_group;");
    }

    // epilogue
#pragma unroll
    for (int mi = 0; mi < 4; mi++)
#pragma unroll
        for (int ni = 0; ni < 4; ni++) {
            int r = m0 + wm * 64 + mi * 16 + (lane >> 2);
            int col = n0 + wn * 32 + ni * 8 + (lane & 3) * 2;
            float2 v0 = make_float2(c[mi][ni][0], c[mi][ni][1]);
            float2 v1 = make_float2(c[mi][ni][2], c[mi][ni][3]);
            long o0 = (long)r * ldc + col;
            long o1 = (long)(r + 8) * ldc + col;
            if (EPI == 1) {
                float2 d0 = *(const float2*)(D + o0);
                float2 d1 = *(const float2*)(D + o1);
                v0.x += d0.x; v0.y += d0.y; v1.x += d1.x; v1.y += d1.y;
            }
            if (EPI == 2) {
                float2 bb = *(const float2*)(bias + col);
                v0.x += bb.x; v0.y += bb.y; v1.x += bb.x; v1.y += bb.y;
            }
            *(float2*)(C + o0) = v0;
            *(float2*)(C + o1) = v1;
        }
}

// ---------------- fp32 SGEMM (att @ V) ----------------
#define STORE_AT(buf, v) do { As[buf][acol+0][arow]=(v).x; As[buf][acol+1][arow]=(v).y; \
                              As[buf][acol+2][arow]=(v).z; As[buf][acol+3][arow]=(v).w; } while(0)

template <int EPI>
__global__ __launch_bounds__(256)
void sgemm_nn(int M, int N, int K,
              const float* __restrict__ A, int lda, long batA,
              const float* __restrict__ B, int ldb, long batB,
              float* __restrict__ C, int ldc, long batC,
              const float* __restrict__ D, long batD,
              const float* __restrict__ bias) {
    int bz = blockIdx.z;
    A += (long)bz * batA; B += (long)bz * batB; C += (long)bz * batC;
    if (EPI == 1) D += (long)bz * batD;

    const int m0 = blockIdx.y * 128;
    const int n0 = blockIdx.x * 128;
    const int tid = threadIdx.x;

    __shared__ float As[2][8][128];
    __shared__ float Bs[2][8][128];

    const int arow = tid >> 1;
    const int acol = (tid & 1) * 4;
    const int brow = tid >> 5;
    const int bcol = (tid & 31) * 4;
    const int ty = tid >> 4;
    const int tx = tid & 15;

    float acc[8][8];
#pragma unroll
    for (int i = 0; i < 8; i++)
#pragma unroll
        for (int j = 0; j < 8; j++) acc[i][j] = 0.f;

    const float* Ap = A + (long)(m0 + arow) * lda + acol;
    const float* Bp = B + (long)brow * ldb + n0 + bcol;

    const int NT = K / 8;
    float4 av = *(const float4*)Ap;
    float4 bv = *(const float4*)Bp;
    STORE_AT(0, av);
    *(float4*)&Bs[0][brow][bcol] = bv;
    __syncthreads();

    for (int kt = 0; kt < NT; kt++) {
        int cur = kt & 1;
        float4 a2, b2;
        if (kt + 1 < NT) {
            a2 = *(const float4*)(Ap + (kt + 1) * 8);
            b2 = *(const float4*)(Bp + (long)(kt + 1) * 8 * ldb);
        }
#pragma unroll
        for (int k = 0; k < 8; k++) {
            float a[8], b[8];
            *(float4*)&a[0] = *(const float4*)&As[cur][k][ty * 8];
            *(float4*)&a[4] = *(const float4*)&As[cur][k][ty * 8 + 4];
            *(float4*)&b[0] = *(const float4*)&Bs[cur][k][tx * 8];
            *(float4*)&b[4] = *(const float4*)&Bs[cur][k][tx * 8 + 4];
#pragma unroll
            for (int i = 0; i < 8; i++)
#pragma unroll
                for (int j = 0; j < 8; j++) acc[i][j] = fmaf(a[i], b[j], acc[i][j]);
        }
        if (kt + 1 < NT) {
            int nx = cur ^ 1;
            STORE_AT(nx, a2);
            *(float4*)&Bs[nx][brow][bcol] = b2;
        }
        __syncthreads();
    }

#pragma unroll
    for (int i = 0; i < 8; i++) {
        long row = m0 + ty * 8 + i;
        long off = row * ldc + n0 + tx * 8;
#pragma unroll
        for (int j = 0; j < 8; j++) {
            float v = acc[i][j];
            if (EPI == 1) v += D[off + j];
            if (EPI == 2) v += bias[n0 + tx * 8 + j];
            C[off + j] = v;
        }
    }
}

// ---------------- scores kernel: NT GEMM + scale + causal mask ----------------
__global__ __launch_bounds__(256)
void scores_kernel(const float* __restrict__ Q, const float* __restrict__ Kx,
                   float* __restrict__ Att) {
    int h = blockIdx.z;
    const float* A = Q + h * HEAD_DIM;
    const float* B = Kx + h * HEAD_DIM;
    float* C = Att + (long)h * S_LEN * S_LEN;

    const int m0 = blockIdx.y * 128;
    const int n0 = blockIdx.x * 128;
    const int tid = threadIdx.x;
    const int ty = tid >> 4;
    const int tx = tid & 15;

    if (n0 > m0 + 127) {  // fully masked tile
#pragma unroll
        for (int i = 0; i < 8; i++) {
            long off = (long)(m0 + ty * 8 + i) * S_LEN + n0 + tx * 8;
#pragma unroll
            for (int j = 0; j < 8; j++) C[off + j] = -1e9f;
        }
        return;
    }

    __shared__ float As[2][8][128];
    __shared__ float Bs[2][8][128];
    const int arow = tid >> 1;
    const int acol = (tid & 1) * 4;

    const float* Ap = A + (long)(m0 + arow) * H_DIM + acol;
    const float* Bp = B + (long)(n0 + arow) * H_DIM + acol;

    float acc[8][8];
#pragma unroll
    for (int i = 0; i < 8; i++)
#pragma unroll
        for (int j = 0; j < 8; j++) acc[i][j] = 0.f;

    float4 av = *(const float4*)Ap;
    float4 bv = *(const float4*)Bp;
    STORE_AT(0, av);
    Bs[0][acol + 0][arow] = bv.x; Bs[0][acol + 1][arow] = bv.y;
    Bs[0][acol + 2][arow] = bv.z; Bs[0][acol + 3][arow] = bv.w;
    __syncthreads();

    const int NT = HEAD_DIM / 8;  // 16
    for (int kt = 0; kt < NT; kt++) {
        int cur = kt & 1;
        float4 a2, b2;
        if (kt + 1 < NT) {
            a2 = *(const float4*)(Ap + (kt + 1) * 8);
            b2 = *(const float4*)(Bp + (kt + 1) * 8);
        }
#pragma unroll
        for (int k = 0; k < 8; k++) {
            float a[8], b[8];
            *(float4*)&a[0] = *(const float4*)&As[cur][k][ty * 8];
            *(float4*)&a[4] = *(const float4*)&As[cur][k][ty * 8 + 4];
            *(float4*)&b[0] = *(const float4*)&Bs[cur][k][tx * 8];
            *(float4*)&b[4] = *(const float4*)&Bs[cur][k][tx * 8 + 4];
#pragma unroll
            for (int i = 0; i < 8; i++)
#pragma unroll
                for (int j = 0; j < 8; j++) acc[i][j] = fmaf(a[i], b[j], acc[i][j]);
        }
        if (kt + 1 < NT) {
            int nx = cur ^ 1;
            STORE_AT(nx, a2);
            Bs[nx][acol + 0][arow] = b2.x; Bs[nx][acol + 1][arow] = b2.y;
            Bs[nx][acol + 2][arow] = b2.z; Bs[nx][acol + 3][arow] = b2.w;
        }
        __syncthreads();
    }

    const float sc = 0.08838834764831845f;  // 1/sqrt(128)
#pragma unroll
    for (int i = 0; i < 8; i++) {
        int row = m0 + ty * 8 + i;
        long off = (long)row * S_LEN + n0 + tx * 8;
#pragma unroll
        for (int j = 0; j < 8; j++) {
            int col = n0 + tx * 8 + j;
            C[off + j] = (col <= row) ? acc[i][j] * sc : -1e9f;
        }
    }
}

// ---------------- host launch ----------------
static inline void do_split(const float* src, __nv_bfloat16* hi, __nv_bfloat16* lo, long n) {
    long n4 = n / 4;
    split_kernel<<<(unsigned)((n4 + 255) / 256), 256>>>(src, hi, lo, n4);
}

extern "C" void kernel_launch(void* const* d_in, const int* in_sizes, int n_in,
                              void* d_out, int out_size) {
    const int*   x     = (const int*)d_in[0];
    const float* embed = (const float*)d_in[1];
    const float* Wq    = (const float*)d_in[2];
    const float* Wk    = (const float*)d_in[3];
    const float* Wv    = (const float*)d_in[4];
    const float* Wo    = (const float*)d_in[5];
    const float* Wg    = (const float*)d_in[6];
    const float* Wu    = (const float*)d_in[7];
    const float* Wd    = (const float*)d_in[8];
    const float* ln1   = (const float*)d_in[9];
    const float* ln2   = (const float*)d_in[10];
    const float* lnf   = (const float*)d_in[11];
    const float* Wout  = (const float*)d_in[12];
    const float* bout  = (const float*)d_in[13];
    float* out = (float*)d_out;

    float* ws = nullptr;
    cudaGetSymbolAddress((void**)&ws, g_ws);
    float* hb = ws + OFF_H;
    float* ab = ws + OFF_A;
    float* qb = ws + OFF_Q;
    float* kb = ws + OFF_K;
    float* vb = ws + OFF_V;
    float* ob = ws + OFF_O;
    float* gb = ws + OFF_G;
    float* ub = ws + OFF_U;
    float* att = ws + OFF_ATT;

    __nv_bfloat16 *ahi, *alo, *bhi, *blo;
    cudaGetSymbolAddress((void**)&ahi, g_ahi);
    cudaGetSymbolAddress((void**)&alo, g_alo);
    cudaGetSymbolAddress((void**)&bhi, g_bhi);
    cudaGetSymbolAddress((void**)&blo, g_blo);

    cudaFuncSetAttribute(bgemm<0>, cudaFuncAttributeMaxDynamicSharedMemorySize, BG_SMEM);
    cudaFuncSetAttribute(bgemm<1>, cudaFuncAttributeMaxDynamicSharedMemorySize, BG_SMEM);
    cudaFuncSetAttribute(bgemm<2>, cudaFuncAttributeMaxDynamicSharedMemorySize, BG_SMEM);

    const dim3 blk(256);

    embed_kernel<<<(S_LEN * H_DIM) / 256, blk>>>(x, embed, hb);

    for (int l = 0; l < N_LAYERS; l++) {
        const float* wq = Wq + (long)l * H_DIM * H_DIM;
        const float* wk = Wk + (long)l * H_DIM * H_DIM;
        const float* wv = Wv + (long)l * H_DIM * H_DIM;
        const float* wo = Wo + (long)l * H_DIM * H_DIM;
        const float* wg = Wg + (long)l * H_DIM * FFN_DIM;
        const float* wu = Wu + (long)l * H_DIM * FFN_DIM;
        const float* wd = Wd + (long)l * FFN_DIM * H_DIM;

        rmsnorm_kernel<<<S_LEN, blk>>>(hb, ln1 + (long)l * H_DIM, ab);
        do_split(ab, ahi, alo, SZ_SH);

        dim3 gQ(H_DIM / 128, S_LEN / 128);
        do_split(wq, bhi, blo, (long)H_DIM * H_DIM);
        bgemm<0><<<gQ, blk, BG_SMEM>>>(H_DIM, ahi, alo, bhi, blo, H_DIM,
                                       qb, H_DIM, nullptr, nullptr);
        do_split(wk, bhi, blo, (long)H_DIM * H_DIM);
        bgemm<0><<<gQ, blk, BG_SMEM>>>(H_DIM, ahi, alo, bhi, blo, H_DIM,
                                       kb, H_DIM, nullptr, nullptr);
        do_split(wv, bhi, blo, (long)H_DIM * H_DIM);
        bgemm<0><<<gQ, blk, BG_SMEM>>>(H_DIM, ahi, alo, bhi, blo, H_DIM,
                                       vb, H_DIM, nullptr, nullptr);

        rope_kernel<<<(S_LEN * N_HEADS * 64) / 256, blk>>>(qb);
        rope_kernel<<<(S_LEN * N_HEADS * 64) / 256, blk>>>(kb);

        dim3 gS(S_LEN / 128, S_LEN / 128, N_HEADS);
        scores_kernel<<<gS, blk>>>(qb, kb, att);

        softmax_kernel<<<N_HEADS * S_LEN, blk>>>(att);

        dim3 gAV(1, S_LEN / 128, N_HEADS);
        sgemm_nn<0><<<gAV, blk>>>(S_LEN, HEAD_DIM, S_LEN,
                                  att, S_LEN, (long)S_LEN * S_LEN,
                                  vb, H_DIM, (long)HEAD_DIM,
                                  ob, H_DIM, (long)HEAD_DIM, nullptr, 0, nullptr);

        do_split(ob, ahi, alo, SZ_SH);
        do_split(wo, bhi, blo, (long)H_DIM * H_DIM);
        bgemm<1><<<gQ, blk, BG_SMEM>>>(H_DIM, ahi, alo, bhi, blo, H_DIM,
                                       hb, H_DIM, hb, nullptr);

        rmsnorm_kernel<<<S_LEN, blk>>>(hb, ln2 + (long)l * H_DIM, ab);
        do_split(ab, ahi, alo, SZ_SH);

        dim3 gF(FFN_DIM / 128, S_LEN / 128);
        do_split(wg, bhi, blo, (long)H_DIM * FFN_DIM);
        bgemm<0><<<gF, blk, BG_SMEM>>>(H_DIM, ahi, alo, bhi, blo, FFN_DIM,
                                       gb, FFN_DIM, nullptr, nullptr);
        do_split(wu, bhi, blo, (long)H_DIM * FFN_DIM);
        bgemm<0><<<gF, blk, BG_SMEM>>>(H_DIM, ahi, alo, bhi, blo, FFN_DIM,
                                       ub, FFN_DIM, nullptr, nullptr);

        silu_mul_kernel<<<(S_LEN * (long)FFN_DIM) / 256, blk>>>(gb, ub, gb);

        do_split(gb, ahi, alo, SZ_SF);
        do_split(wd, bhi, blo, (long)FFN_DIM * H_DIM);
        bgemm<1><<<gQ, blk, BG_SMEM>>>(FFN_DIM, ahi, alo, bhi, blo, H_DIM,
                                       hb, H_DIM, hb, nullptr);
    }

    rmsnorm_kernel<<<S_LEN, blk>>>(hb, lnf, ab);
    do_split(ab, ahi, alo, SZ_SH);
    do_split(Wout, bhi, blo, (long)H_DIM * OUT_DIM);

    dim3 gO(OUT_DIM / 128, S_LEN / 128);
    bgemm<2><<<gO, blk, BG_SMEM>>>(H_DIM, ahi, alo, bhi, blo, OUT_DIM,
                                   out, OUT_DIM, nullptr, bout);
}